// round 1
// baseline (speedup 1.0000x reference)
#include <cuda_runtime.h>
#include <math.h>

// ---------------- problem constants ----------------
#define B_   8
#define L_   2048
#define D_   256
#define DIN_ 512
#define NSS  64          // N (state dim)
#define PSS  64          // P (head dim)
#define H_   8
#define M_   (B_ * L_)   // 16384 rows
#define XW_  (H_ + 2 * NSS)  // 136

// ---------------- scratch (device globals — no allocations allowed) ----------------
__device__ float  g_xln[M_ * D_];     // LN(src)
__device__ float  g_u0 [M_ * DIN_];   // xln @ W_in
__device__ float  g_u  [M_ * DIN_];   // gelu(conv(u0)+b)
__device__ float  g_dbc[M_ * XW_];    // u @ W_xproj
__device__ float2 g_dd [M_ * H_];     // (decay, dt)
__device__ float  g_y  [M_ * DIN_];   // scan output + Ds*xh
__device__ float  g_yln[M_ * DIN_];   // LN(y)

// ---------------- packed f32x2 helpers (Blackwell FFMA2) ----------------
typedef unsigned long long u64;

__device__ __forceinline__ u64 pk2(float lo, float hi) {
    u64 r;
    asm("mov.b64 %0, {%1, %2};" : "=l"(r)
        : "r"(__float_as_uint(lo)), "r"(__float_as_uint(hi)));
    return r;
}
__device__ __forceinline__ u64 fma2(u64 a, u64 b, u64 c) {
    u64 d;
    asm("fma.rn.f32x2 %0, %1, %2, %3;" : "=l"(d) : "l"(a), "l"(b), "l"(c));
    return d;
}
__device__ __forceinline__ u64 mul2(u64 a, u64 b) {
    u64 d;
    asm("mul.rn.f32x2 %0, %1, %2;" : "=l"(d) : "l"(a), "l"(b));
    return d;
}
__device__ __forceinline__ float2 unpk(u64 v) {
    unsigned lo, hi;
    asm("mov.b64 {%0, %1}, %2;" : "=r"(lo), "=r"(hi) : "l"(v));
    return make_float2(__uint_as_float(lo), __uint_as_float(hi));
}

// ---------------- LayerNorm: one warp per row ----------------
template <int W>
__global__ void ln_kernel(const float* __restrict__ in,
                          const float* __restrict__ gw,
                          const float* __restrict__ gb,
                          float* __restrict__ out) {
    const int warp = threadIdx.x >> 5, lane = threadIdx.x & 31;
    const int row = blockIdx.x * (blockDim.x >> 5) + warp;
    const float* p = in + (size_t)row * W;
    constexpr int C = W / 128;
    float4 v[C];
    float s = 0.f, s2 = 0.f;
#pragma unroll
    for (int c = 0; c < C; c++) {
        v[c] = *(const float4*)(p + c * 128 + lane * 4);
        s  += v[c].x + v[c].y + v[c].z + v[c].w;
        s2 += v[c].x * v[c].x + v[c].y * v[c].y + v[c].z * v[c].z + v[c].w * v[c].w;
    }
#pragma unroll
    for (int o = 16; o > 0; o >>= 1) {
        s  += __shfl_xor_sync(0xffffffffu, s, o);
        s2 += __shfl_xor_sync(0xffffffffu, s2, o);
    }
    const float mean = s * (1.f / W);
    const float var  = s2 * (1.f / W) - mean * mean;
    const float inv  = rsqrtf(var + 1e-5f);
    float* q = out + (size_t)row * W;
#pragma unroll
    for (int c = 0; c < C; c++) {
        const int i = c * 128 + lane * 4;
        float4 w4 = *(const float4*)(gw + i);
        float4 b4 = *(const float4*)(gb + i);
        float4 r;
        r.x = (v[c].x - mean) * inv * w4.x + b4.x;
        r.y = (v[c].y - mean) * inv * w4.y + b4.y;
        r.z = (v[c].z - mean) * inv * w4.z + b4.z;
        r.w = (v[c].w - mean) * inv * w4.w + b4.w;
        *(float4*)(q + i) = r;
    }
}

// ---------------- SGEMM with f32x2 accumulators ----------------
// C[M,N] = A[M,K] @ B[K,N] (+ addend). BM=128 BN=64 BK=16, 256 thr, 8x4 microtile.
#define BM 128
#define BN 64
#define BK 16
#define APAD 4

__device__ __forceinline__ void sgemm_dev(int M, int N, int K,
                                          const float* __restrict__ A,
                                          const float* __restrict__ Bmat,
                                          float* __restrict__ C,
                                          const float* __restrict__ addend) {
    __shared__ __align__(16) float As[BK][BM + APAD];
    __shared__ __align__(16) float Bs[BK][BN];

    const int tid = threadIdx.x;
    const int bm = blockIdx.y * BM;
    const int bn = blockIdx.x * BN;
    const int ty = tid >> 4;          // 0..15 -> rows ty*8..+7
    const int tx = tid & 15;          // 0..15 -> cols tx*4..+3
    const int aR = tid >> 2;          // 0..63
    const int aC = (tid & 3) * 4;     // 0,4,8,12
    const int bR = tid >> 4;          // 0..15
    const int bC = (tid & 15) * 4;    // 0..60
    const bool bvalid = (bn + bC) < N;

    u64 acc[4][4];
#pragma unroll
    for (int i = 0; i < 4; i++)
#pragma unroll
        for (int j = 0; j < 4; j++) acc[i][j] = 0ull;

    const float* A0 = A + (size_t)(bm + aR) * K;
    const float* A1 = A + (size_t)(bm + aR + 64) * K;

    const int nk = K / BK;
    float4 ra0 = *(const float4*)(A0 + aC);
    float4 ra1 = *(const float4*)(A1 + aC);
    float4 rb  = bvalid ? *(const float4*)(Bmat + (size_t)bR * N + bn + bC)
                        : make_float4(0.f, 0.f, 0.f, 0.f);

    for (int kt = 0; kt < nk; kt++) {
        __syncthreads();
        As[aC + 0][aR]      = ra0.x; As[aC + 1][aR]      = ra0.y;
        As[aC + 2][aR]      = ra0.z; As[aC + 3][aR]      = ra0.w;
        As[aC + 0][aR + 64] = ra1.x; As[aC + 1][aR + 64] = ra1.y;
        As[aC + 2][aR + 64] = ra1.z; As[aC + 3][aR + 64] = ra1.w;
        *(float4*)&Bs[bR][bC] = rb;
        __syncthreads();

        if (kt + 1 < nk) {
            const int ko = (kt + 1) * BK;
            ra0 = *(const float4*)(A0 + ko + aC);
            ra1 = *(const float4*)(A1 + ko + aC);
            if (bvalid)
                rb = *(const float4*)(Bmat + (size_t)(ko + bR) * N + bn + bC);
        }

#pragma unroll
        for (int k = 0; k < BK; k++) {
            const u64* pA = (const u64*)&As[k][ty * 8];
            u64 a2[4];
            a2[0] = pA[0]; a2[1] = pA[1]; a2[2] = pA[2]; a2[3] = pA[3];
            float4 b4 = *(const float4*)&Bs[k][tx * 4];
            u64 bb[4] = { pk2(b4.x, b4.x), pk2(b4.y, b4.y),
                          pk2(b4.z, b4.z), pk2(b4.w, b4.w) };
#pragma unroll
            for (int i = 0; i < 4; i++)
#pragma unroll
                for (int j = 0; j < 4; j++)
                    acc[i][j] = fma2(a2[i], bb[j], acc[i][j]);
        }
    }

    const int col = bn + tx * 4;
    if (col < N) {                    // N % 4 == 0 -> whole float4 valid
#pragma unroll
        for (int i = 0; i < 4; i++) {
            float2 c0 = unpk(acc[i][0]), c1 = unpk(acc[i][1]);
            float2 c2 = unpk(acc[i][2]), c3 = unpk(acc[i][3]);
            const int r0 = bm + ty * 8 + 2 * i;
            const size_t o0 = (size_t)r0 * N + col;
            float4 lo = make_float4(c0.x, c1.x, c2.x, c3.x);
            float4 hi = make_float4(c0.y, c1.y, c2.y, c3.y);
            if (addend) {
                float4 s0 = *(const float4*)(addend + o0);
                float4 s1 = *(const float4*)(addend + o0 + N);
                lo.x += s0.x; lo.y += s0.y; lo.z += s0.z; lo.w += s0.w;
                hi.x += s1.x; hi.y += s1.y; hi.z += s1.z; hi.w += s1.w;
            }
            *(float4*)(C + o0)     = lo;
            *(float4*)(C + o0 + N) = hi;
        }
    }
}

__global__ void __launch_bounds__(256) gemm1_kernel(const float* __restrict__ W_in) {
    sgemm_dev(M_, DIN_, D_, g_xln, W_in, g_u0, nullptr);
}
__global__ void __launch_bounds__(256) gemm2_kernel(const float* __restrict__ W_xproj) {
    sgemm_dev(M_, XW_, DIN_, g_u, W_xproj, g_dbc, nullptr);
}
__global__ void __launch_bounds__(256) gemm3_kernel(const float* __restrict__ W_out,
                                                    const float* __restrict__ src,
                                                    float* __restrict__ out) {
    sgemm_dev(M_, D_, DIN_, g_yln, W_out, out, src);
}

// ---------------- depthwise conv3 + bias + exact GELU ----------------
__global__ void conv_gelu_kernel(const float* __restrict__ cw,
                                 const float* __restrict__ cb) {
    const int idx = blockIdx.x * blockDim.x + threadIdx.x;  // over M_*DIN_
    if (idx >= M_ * DIN_) return;
    const int c = idx & (DIN_ - 1);
    const int m = idx >> 9;
    const int l = m & (L_ - 1);
    const float w0 = cw[c * 3 + 0], w1 = cw[c * 3 + 1], w2 = cw[c * 3 + 2];
    const float xm = (l > 0)      ? g_u0[idx - DIN_] : 0.f;
    const float x0 = g_u0[idx];
    const float xp = (l < L_ - 1) ? g_u0[idx + DIN_] : 0.f;
    const float v = w0 * xm + w1 * x0 + w2 * xp + cb[c];
    g_u[idx] = 0.5f * v * (1.f + erff(v * 0.7071067811865476f));
}

// ---------------- dt = softplus(dbc[:, :H] + bias), decay = exp(dt * -exp(A_log)) ----------------
__global__ void ddt_kernel(const float* __restrict__ dt_bias,
                           const float* __restrict__ A_log) {
    const int idx = blockIdx.x * blockDim.x + threadIdx.x;  // M_*H_
    if (idx >= M_ * H_) return;
    const int h = idx & 7;
    const int m = idx >> 3;
    const float x = g_dbc[(size_t)m * XW_ + h] + dt_bias[h];
    const float dt = (x > 0.f) ? x + log1pf(expf(-x)) : log1pf(expf(x));
    const float dec = expf(-dt * expf(A_log[h]));
    g_dd[idx] = make_float2(dec, dt);
}

// ---------------- selective scan: one CTA per (b,h), state in registers ----------------
// 256 threads: p = t>>2 (0..63), q = t&3 -> n in [q*16, q*16+16).
// gmem -> reg -> smem pipeline, prefetch distance 2, double-buffered smem.
__global__ void __launch_bounds__(256) scan_kernel(const float* __restrict__ Ds) {
    __shared__ __align__(16) float sB[2][NSS];
    __shared__ __align__(16) float sC[2][NSS];
    __shared__ __align__(16) float sX[2][PSS];
    __shared__ float2 sDD[2];

    const int t = threadIdx.x;
    const int b = blockIdx.x >> 3, h = blockIdx.x & 7;
    const size_t mbase = (size_t)b * L_;
    const int p = t >> 2, q = t & 3, n0 = q * 16;
    const int role = t >> 6, li = t & 63;
    const float Dsh = Ds[h];

    const float*  gB = g_dbc + mbase * XW_ + H_ + li;
    const float*  gC = g_dbc + mbase * XW_ + H_ + NSS + li;
    const float*  gX = g_u + mbase * DIN_ + h * PSS + li;
    const float2* gD = g_dd + mbase * H_ + h;

    float v0 = 0.f, v1 = 0.f;
    float2 w0 = make_float2(0.f, 0.f), w1 = w0;

    // prologue: rows 0,1; STS row0; reload slot0 with row2
    if (role == 0)      { v0 = gB[0]; v1 = gB[XW_]; }
    else if (role == 1) { v0 = gC[0]; v1 = gC[XW_]; }
    else if (role == 2) { v0 = gX[0]; v1 = gX[DIN_]; }
    else if (t == 192)  { w0 = gD[0]; w1 = gD[H_]; }

    if (role == 0)      sB[0][li] = v0;
    else if (role == 1) sC[0][li] = v0;
    else if (role == 2) sX[0][li] = v0;
    else if (t == 192)  sDD[0] = w0;

    if (role == 0)      v0 = gB[2 * XW_];
    else if (role == 1) v0 = gC[2 * XW_];
    else if (role == 2) v0 = gX[2 * DIN_];
    else if (t == 192)  w0 = gD[2 * H_];
    __syncthreads();

    u64 hs[8];
#pragma unroll
    for (int j = 0; j < 8; j++) hs[j] = 0ull;

    float* yout = g_y + mbase * DIN_ + h * PSS + p;

    for (int l = 0; l < L_; l++) {
        const int buf = l & 1;
        // stage row l+1 (slot parity (l+1)&1) into buf^1, then prefetch row l+3
        if ((l & 1) == 0) {  // slot 1
            if (role == 0)      sB[buf ^ 1][li] = v1;
            else if (role == 1) sC[buf ^ 1][li] = v1;
            else if (role == 2) sX[buf ^ 1][li] = v1;
            else if (t == 192)  sDD[buf ^ 1] = w1;
            if (l + 3 < L_) {
                const size_t r = (size_t)(l + 3);
                if (role == 0)      v1 = gB[r * XW_];
                else if (role == 1) v1 = gC[r * XW_];
                else if (role == 2) v1 = gX[r * DIN_];
                else if (t == 192)  w1 = gD[r * H_];
            }
        } else {             // slot 0
            if (role == 0)      sB[buf ^ 1][li] = v0;
            else if (role == 1) sC[buf ^ 1][li] = v0;
            else if (role == 2) sX[buf ^ 1][li] = v0;
            else if (t == 192)  sDD[buf ^ 1] = w0;
            if (l + 3 < L_) {
                const size_t r = (size_t)(l + 3);
                if (role == 0)      v0 = gB[r * XW_];
                else if (role == 1) v0 = gC[r * XW_];
                else if (role == 2) v0 = gX[r * DIN_];
                else if (t == 192)  w0 = gD[r * H_];
            }
        }

        // compute step l from shared buf
        const float2 dd = sDD[buf];
        const float xp = sX[buf][p];
        const u64 dec2 = pk2(dd.x, dd.x);
        const float dtx = dd.y * xp;
        const u64 dtx2 = pk2(dtx, dtx);
        const u64* pB = (const u64*)&sB[buf][n0];
        const u64* pC = (const u64*)&sC[buf][n0];
        u64 a0 = 0ull, a1 = 0ull;
#pragma unroll
        for (int j = 0; j < 8; j++) {
            const u64 bb = pB[j];
            const u64 cc = pC[j];
            hs[j] = fma2(hs[j], dec2, mul2(dtx2, bb));
            if (j & 1) a1 = fma2(hs[j], cc, a1);
            else       a0 = fma2(hs[j], cc, a0);
        }
        const float2 f0 = unpk(a0), f1 = unpk(a1);
        float acc = (f0.x + f0.y) + (f1.x + f1.y);
        acc += __shfl_xor_sync(0xffffffffu, acc, 1);
        acc += __shfl_xor_sync(0xffffffffu, acc, 2);
        if (q == 0) yout[(size_t)l * DIN_] = acc + Dsh * xp;
        __syncthreads();
    }
}

// ---------------- output LN wrapper ----------------
__global__ void ln_in_kernel(const float* __restrict__ src,
                             const float* __restrict__ w,
                             const float* __restrict__ b) {
    // delegated via template instantiation below
}

extern "C" void kernel_launch(void* const* d_in, const int* in_sizes, int n_in,
                              void* d_out, int out_size) {
    const float* src     = (const float*)d_in[0];
    const float* ln_w    = (const float*)d_in[1];
    const float* ln_b    = (const float*)d_in[2];
    const float* W_in    = (const float*)d_in[3];
    const float* conv_w  = (const float*)d_in[4];
    const float* conv_b  = (const float*)d_in[5];
    const float* W_xproj = (const float*)d_in[6];
    const float* dt_bias = (const float*)d_in[7];
    const float* A_log   = (const float*)d_in[8];
    const float* Ds      = (const float*)d_in[9];
    const float* oln_w   = (const float*)d_in[10];
    const float* oln_b   = (const float*)d_in[11];
    const float* W_out   = (const float*)d_in[12];
    float* out = (float*)d_out;

    // device-global output targets for LN kernels
    float* xln_ptr = nullptr; float* u0_ptr = nullptr;
    float* y_ptr = nullptr;   float* yln_ptr = nullptr;
    cudaGetSymbolAddress((void**)&xln_ptr, g_xln);
    cudaGetSymbolAddress((void**)&y_ptr,   g_y);
    cudaGetSymbolAddress((void**)&yln_ptr, g_yln);

    // 1) LN over D=256
    ln_kernel<D_><<<M_ / 8, 256>>>(src, ln_w, ln_b, xln_ptr);
    // 2) u0 = xln @ W_in  (16384x256x512)
    gemm1_kernel<<<dim3(DIN_ / BN, M_ / BM), 256>>>(W_in);
    // 3) depthwise conv3 + bias + gelu
    conv_gelu_kernel<<<(M_ * DIN_) / 256, 256>>>(conv_w, conv_b);
    // 4) dbc = u @ W_xproj (16384x512x136)
    gemm2_kernel<<<dim3((XW_ + BN - 1) / BN, M_ / BM), 256>>>(W_xproj);
    // 5) dt / decay
    ddt_kernel<<<(M_ * H_) / 256, 256>>>(dt_bias, A_log);
    // 6) selective scan + Ds*xh  (64 CTAs, one per (b,h))
    scan_kernel<<<B_ * H_, 256>>>(Ds);
    // 7) LN over DIN=512
    ln_kernel<DIN_><<<M_ / 8, 256>>>(y_ptr, oln_w, oln_b, yln_ptr);
    // 8) out = src + yln @ W_out (16384x512x256)
    gemm3_kernel<<<dim3(D_ / BN, M_ / BM), 256>>>(W_out, src, out);
}

// round 5
// speedup vs baseline: 2.7384x; 2.7384x over previous
#include <cuda_runtime.h>
#include <math.h>

// ---------------- problem constants ----------------
#define B_   8
#define L_   2048
#define D_   256
#define DIN_ 512
#define NSS  64          // N (state dim)
#define PSS  64          // P (head dim)
#define H_   8
#define M_   (B_ * L_)   // 16384 rows
#define XW_  (H_ + 2 * NSS)  // 136
#define TC   64          // scan chunk length
#define NC_  (L_ / TC)   // 32 chunks
#define SP   68          // padded smem stride (float4-aligned)

// ---------------- scratch (device globals — no allocations allowed) ----------------
__device__ float  g_xln[M_ * D_];     // LN(src)
__device__ float  g_u0 [M_ * DIN_];   // xln @ W_in
__device__ float  g_u  [M_ * DIN_];   // gelu(conv(u0)+b)
__device__ float  g_dbc[M_ * XW_];    // u @ W_xproj
__device__ float2 g_dd [M_ * H_];     // (log-decay, dt)
__device__ float  g_y  [M_ * DIN_];   // scan output + Ds*xh
__device__ float  g_yln[M_ * DIN_];   // LN(y)
__device__ float  g_S  [B_ * H_ * NC_ * TC * TC];  // chunk contributions [n][p]
__device__ float  g_hst[B_ * H_ * NC_ * TC * TC];  // chunk-start states  [n][p]
__device__ float  g_alpha[B_ * H_ * NC_];          // chunk decay product

// ---------------- packed f32x2 helpers (Blackwell FFMA2) ----------------
typedef unsigned long long u64;

__device__ __forceinline__ u64 pk2(float lo, float hi) {
    u64 r;
    asm("mov.b64 %0, {%1, %2};" : "=l"(r)
        : "r"(__float_as_uint(lo)), "r"(__float_as_uint(hi)));
    return r;
}
__device__ __forceinline__ u64 fma2(u64 a, u64 b, u64 c) {
    u64 d;
    asm("fma.rn.f32x2 %0, %1, %2, %3;" : "=l"(d) : "l"(a), "l"(b), "l"(c));
    return d;
}
__device__ __forceinline__ u64 mul2(u64 a, u64 b) {
    u64 d;
    asm("mul.rn.f32x2 %0, %1, %2;" : "=l"(d) : "l"(a), "l"(b));
    return d;
}
__device__ __forceinline__ float2 unpk(u64 v) {
    unsigned lo, hi;
    asm("mov.b64 {%0, %1}, %2;" : "=r"(lo), "=r"(hi) : "l"(v));
    return make_float2(__uint_as_float(lo), __uint_as_float(hi));
}

// ---------------- LayerNorm: one warp per row ----------------
template <int W>
__global__ void ln_kernel(const float* __restrict__ in,
                          const float* __restrict__ gw,
                          const float* __restrict__ gb,
                          float* __restrict__ out) {
    const int warp = threadIdx.x >> 5, lane = threadIdx.x & 31;
    const int row = blockIdx.x * (blockDim.x >> 5) + warp;
    const float* p = in + (size_t)row * W;
    constexpr int C = W / 128;
    float4 v[C];
    float s = 0.f, s2 = 0.f;
#pragma unroll
    for (int c = 0; c < C; c++) {
        v[c] = *(const float4*)(p + c * 128 + lane * 4);
        s  += v[c].x + v[c].y + v[c].z + v[c].w;
        s2 += v[c].x * v[c].x + v[c].y * v[c].y + v[c].z * v[c].z + v[c].w * v[c].w;
    }
#pragma unroll
    for (int o = 16; o > 0; o >>= 1) {
        s  += __shfl_xor_sync(0xffffffffu, s, o);
        s2 += __shfl_xor_sync(0xffffffffu, s2, o);
    }
    const float mean = s * (1.f / W);
    const float var  = s2 * (1.f / W) - mean * mean;
    const float inv  = rsqrtf(var + 1e-5f);
    float* q = out + (size_t)row * W;
#pragma unroll
    for (int c = 0; c < C; c++) {
        const int i = c * 128 + lane * 4;
        float4 w4 = *(const float4*)(gw + i);
        float4 b4 = *(const float4*)(gb + i);
        float4 r;
        r.x = (v[c].x - mean) * inv * w4.x + b4.x;
        r.y = (v[c].y - mean) * inv * w4.y + b4.y;
        r.z = (v[c].z - mean) * inv * w4.z + b4.z;
        r.w = (v[c].w - mean) * inv * w4.w + b4.w;
        *(float4*)(q + i) = r;
    }
}

// ---------------- SGEMM with f32x2 accumulators ----------------
#define BM 128
#define BN 64
#define BK 16
#define APAD 4

__device__ __forceinline__ void sgemm_dev(int M, int N, int K,
                                          const float* __restrict__ A,
                                          const float* __restrict__ Bmat,
                                          float* __restrict__ C,
                                          const float* __restrict__ addend) {
    __shared__ __align__(16) float As[BK][BM + APAD];
    __shared__ __align__(16) float Bs[BK][BN];

    const int tid = threadIdx.x;
    const int bm = blockIdx.y * BM;
    const int bn = blockIdx.x * BN;
    const int ty = tid >> 4;
    const int tx = tid & 15;
    const int aR = tid >> 2;
    const int aC = (tid & 3) * 4;
    const int bR = tid >> 4;
    const int bC = (tid & 15) * 4;
    const bool bvalid = (bn + bC) < N;

    u64 acc[4][4];
#pragma unroll
    for (int i = 0; i < 4; i++)
#pragma unroll
        for (int j = 0; j < 4; j++) acc[i][j] = 0ull;

    const float* A0 = A + (size_t)(bm + aR) * K;
    const float* A1 = A + (size_t)(bm + aR + 64) * K;

    const int nk = K / BK;
    float4 ra0 = *(const float4*)(A0 + aC);
    float4 ra1 = *(const float4*)(A1 + aC);
    float4 rb  = bvalid ? *(const float4*)(Bmat + (size_t)bR * N + bn + bC)
                        : make_float4(0.f, 0.f, 0.f, 0.f);

    for (int kt = 0; kt < nk; kt++) {
        __syncthreads();
        As[aC + 0][aR]      = ra0.x; As[aC + 1][aR]      = ra0.y;
        As[aC + 2][aR]      = ra0.z; As[aC + 3][aR]      = ra0.w;
        As[aC + 0][aR + 64] = ra1.x; As[aC + 1][aR + 64] = ra1.y;
        As[aC + 2][aR + 64] = ra1.z; As[aC + 3][aR + 64] = ra1.w;
        *(float4*)&Bs[bR][bC] = rb;
        __syncthreads();

        if (kt + 1 < nk) {
            const int ko = (kt + 1) * BK;
            ra0 = *(const float4*)(A0 + ko + aC);
            ra1 = *(const float4*)(A1 + ko + aC);
            if (bvalid)
                rb = *(const float4*)(Bmat + (size_t)(ko + bR) * N + bn + bC);
        }

#pragma unroll
        for (int k = 0; k < BK; k++) {
            const u64* pA = (const u64*)&As[k][ty * 8];
            u64 a2[4];
            a2[0] = pA[0]; a2[1] = pA[1]; a2[2] = pA[2]; a2[3] = pA[3];
            float4 b4 = *(const float4*)&Bs[k][tx * 4];
            u64 bb[4] = { pk2(b4.x, b4.x), pk2(b4.y, b4.y),
                          pk2(b4.z, b4.z), pk2(b4.w, b4.w) };
#pragma unroll
            for (int i = 0; i < 4; i++)
#pragma unroll
                for (int j = 0; j < 4; j++)
                    acc[i][j] = fma2(a2[i], bb[j], acc[i][j]);
        }
    }

    const int col = bn + tx * 4;
    if (col < N) {
#pragma unroll
        for (int i = 0; i < 4; i++) {
            float2 c0 = unpk(acc[i][0]), c1 = unpk(acc[i][1]);
            float2 c2 = unpk(acc[i][2]), c3 = unpk(acc[i][3]);
            const int r0 = bm + ty * 8 + 2 * i;
            const size_t o0 = (size_t)r0 * N + col;
            float4 lo = make_float4(c0.x, c1.x, c2.x, c3.x);
            float4 hi = make_float4(c0.y, c1.y, c2.y, c3.y);
            if (addend) {
                float4 s0 = *(const float4*)(addend + o0);
                float4 s1 = *(const float4*)(addend + o0 + N);
                lo.x += s0.x; lo.y += s0.y; lo.z += s0.z; lo.w += s0.w;
                hi.x += s1.x; hi.y += s1.y; hi.z += s1.z; hi.w += s1.w;
            }
            *(float4*)(C + o0)     = lo;
            *(float4*)(C + o0 + N) = hi;
        }
    }
}

__global__ void __launch_bounds__(256) gemm1_kernel(const float* __restrict__ W_in) {
    sgemm_dev(M_, DIN_, D_, g_xln, W_in, g_u0, nullptr);
}
__global__ void __launch_bounds__(256) gemm2_kernel(const float* __restrict__ W_xproj) {
    sgemm_dev(M_, XW_, DIN_, g_u, W_xproj, g_dbc, nullptr);
}
__global__ void __launch_bounds__(256) gemm3_kernel(const float* __restrict__ W_out,
                                                    const float* __restrict__ src,
                                                    float* __restrict__ out) {
    sgemm_dev(M_, D_, DIN_, g_yln, W_out, out, src);
}

// ---------------- depthwise conv3 + bias + exact GELU ----------------
__global__ void conv_gelu_kernel(const float* __restrict__ cw,
                                 const float* __restrict__ cb) {
    const int idx = blockIdx.x * blockDim.x + threadIdx.x;
    if (idx >= M_ * DIN_) return;
    const int c = idx & (DIN_ - 1);
    const int m = idx >> 9;
    const int l = m & (L_ - 1);
    const float w0 = cw[c * 3 + 0], w1 = cw[c * 3 + 1], w2 = cw[c * 3 + 2];
    const float xm = (l > 0)      ? g_u0[idx - DIN_] : 0.f;
    const float x0 = g_u0[idx];
    const float xp = (l < L_ - 1) ? g_u0[idx + DIN_] : 0.f;
    const float v = w0 * xm + w1 * x0 + w2 * xp + cb[c];
    g_u[idx] = 0.5f * v * (1.f + erff(v * 0.7071067811865476f));
}

// ---------------- (la = -dt*exp(A_log), dt = softplus(dbc[:, :H] + bias)) ----------------
__global__ void ddt_kernel(const float* __restrict__ dt_bias,
                           const float* __restrict__ A_log) {
    const int idx = blockIdx.x * blockDim.x + threadIdx.x;
    if (idx >= M_ * H_) return;
    const int h = idx & 7;
    const int m = idx >> 3;
    const float x = g_dbc[(size_t)m * XW_ + h] + dt_bias[h];
    const float dt = (x > 0.f) ? x + log1pf(expf(-x)) : log1pf(expf(x));
    const float la = -dt * expf(A_log[h]);
    g_dd[idx] = make_float2(la, dt);
}

// ================= chunked selective scan =================
// Kernel A: per-(b,h,chunk) state contribution S[n][p] = sum_k e^{S_end-S_k} dt_k x_k[p] B_k[n]
__global__ void __launch_bounds__(256) chunk_state_kernel() {
    __shared__ __align__(16) float sBt[TC][SP];   // Bt[n][k]
    __shared__ __align__(16) float sXc[TC][SP];   // scaled X[k][p]
    __shared__ float sScan[TC], sDt[TC];

    const int c = blockIdx.x, h = blockIdx.y, b = blockIdx.z;
    const int t = threadIdx.x;
    const size_t row0 = (size_t)b * L_ + (size_t)c * TC;
    const int bhc = (b * H_ + h) * NC_ + c;

    if (t < TC) {
        float2 dd = g_dd[(row0 + t) * H_ + h];
        sScan[t] = dd.x; sDt[t] = dd.y;
    }
    __syncthreads();
    if (t == 0) {
        float s = 0.f;
#pragma unroll 1
        for (int i = 0; i < TC; i++) { s += sScan[i]; sScan[i] = s; }
    }
    __syncthreads();

    // load B transposed + X scaled
    {
        const int k = t >> 2;
        const int n0 = (t & 3) * 16;
        const float* bsrc = g_dbc + (row0 + k) * XW_ + H_ + n0;
        const float Send = sScan[TC - 1];
        const float coef = __expf(Send - sScan[k]) * sDt[k];
        const float* xsrc = g_u + (row0 + k) * DIN_ + h * PSS + n0;
#pragma unroll
        for (int q = 0; q < 4; q++) {
            float4 v = *(const float4*)(bsrc + q * 4);
            const int n = n0 + q * 4;
            sBt[n + 0][k] = v.x; sBt[n + 1][k] = v.y;
            sBt[n + 2][k] = v.z; sBt[n + 3][k] = v.w;
            float4 x = *(const float4*)(xsrc + q * 4);
            x.x *= coef; x.y *= coef; x.z *= coef; x.w *= coef;
            *(float4*)&sXc[k][n0 + q * 4] = x;
        }
    }
    if (t == 0) g_alpha[bhc] = __expf(sScan[TC - 1]);
    __syncthreads();

    const int ty = t >> 4, tx = t & 15;
    u64 acc[4][2];
#pragma unroll
    for (int r = 0; r < 4; r++) { acc[r][0] = 0ull; acc[r][1] = 0ull; }
#pragma unroll
    for (int k = 0; k < TC; k++) {
        const u64 x0 = *(const u64*)&sXc[k][tx * 4];
        const u64 x1 = *(const u64*)&sXc[k][tx * 4 + 2];
#pragma unroll
        for (int r = 0; r < 4; r++) {
            const float bv = sBt[ty * 4 + r][k];
            const u64 b2 = pk2(bv, bv);
            acc[r][0] = fma2(b2, x0, acc[r][0]);
            acc[r][1] = fma2(b2, x1, acc[r][1]);
        }
    }
    float* dst = g_S + (size_t)bhc * (TC * TC);
#pragma unroll
    for (int r = 0; r < 4; r++) {
        const int n = ty * 4 + r;
        float2 f0 = unpk(acc[r][0]), f1 = unpk(acc[r][1]);
        *(float4*)(dst + n * TC + tx * 4) = make_float4(f0.x, f0.y, f1.x, f1.y);
    }
}

// Kernel B: sequential state pass over chunks (cheap): writes h_start per chunk
__global__ void __launch_bounds__(256) state_pass_kernel() {
    const int bh = blockIdx.x;
    const int t = threadIdx.x;
    float4 hv[4];
#pragma unroll
    for (int q = 0; q < 4; q++) hv[q] = make_float4(0.f, 0.f, 0.f, 0.f);
    const size_t base = (size_t)bh * NC_ * (TC * TC);
#pragma unroll 1
    for (int c = 0; c < NC_; c++) {
        const float alpha = g_alpha[bh * NC_ + c];
        float* hst = g_hst + base + (size_t)c * (TC * TC);
        const float* S = g_S + base + (size_t)c * (TC * TC);
#pragma unroll
        for (int q = 0; q < 4; q++) {
            const int off = (q * 256 + t) * 4;
            *(float4*)(hst + off) = hv[q];
            float4 s = *(const float4*)(S + off);
            hv[q].x = alpha * hv[q].x + s.x;
            hv[q].y = alpha * hv[q].y + s.y;
            hv[q].z = alpha * hv[q].z + s.z;
            hv[q].w = alpha * hv[q].w + s.w;
        }
    }
}

// Kernel C: per-(b,h,chunk) outputs:
// y(i,p) = [maskedGram @ X](i,p) + e^{S_i} [C @ h_startT](i,p) + Ds*x(i,p)
__global__ void __launch_bounds__(256) chunk_output_kernel(const float* __restrict__ Ds) {
    extern __shared__ __align__(16) float dynsmem[];
    float* sC  = dynsmem;                 // [TC][SP]  C[i][n]
    float* sB2 = sC + TC * SP;            // [TC][SP]  Bt / Ht / X
    float* sG  = sB2 + TC * SP;           // [TC][SP]  masked gram
    float* sScan = sG + TC * SP;          // [TC]
    float* sDt   = sScan + TC;            // [TC]
    float* sE    = sDt + TC;              // [TC]

    const int c = blockIdx.x, h = blockIdx.y, b = blockIdx.z;
    const int t = threadIdx.x;
    const size_t row0 = (size_t)b * L_ + (size_t)c * TC;
    const int bhc = (b * H_ + h) * NC_ + c;

    if (t < TC) {
        float2 dd = g_dd[(row0 + t) * H_ + h];
        sScan[t] = dd.x; sDt[t] = dd.y;
    }
    __syncthreads();
    if (t == 0) {
        float s = 0.f;
#pragma unroll 1
        for (int i = 0; i < TC; i++) { s += sScan[i]; sScan[i] = s; }
    }
    __syncthreads();
    if (t < TC) sE[t] = __expf(sScan[t]);

    // load C[i][n] direct, B transposed into sB2[n][k]
    {
        const int k = t >> 2;
        const int n0 = (t & 3) * 16;
        const float* csrc = g_dbc + (row0 + k) * XW_ + H_ + NSS + n0;
        const float* bsrc = g_dbc + (row0 + k) * XW_ + H_ + n0;
#pragma unroll
        for (int q = 0; q < 4; q++) {
            *(float4*)&sC[k * SP + n0 + q * 4] = *(const float4*)(csrc + q * 4);
            float4 v = *(const float4*)(bsrc + q * 4);
            const int n = n0 + q * 4;
            sB2[(n + 0) * SP + k] = v.x; sB2[(n + 1) * SP + k] = v.y;
            sB2[(n + 2) * SP + k] = v.z; sB2[(n + 3) * SP + k] = v.w;
        }
    }
    __syncthreads();

    const int ty = t >> 4, tx = t & 15;

    // gram: g(i,k) = sum_n C[i][n] B[k][n]
    u64 gacc[4][2];
#pragma unroll
    for (int r = 0; r < 4; r++) { gacc[r][0] = 0ull; gacc[r][1] = 0ull; }
#pragma unroll
    for (int n = 0; n < TC; n++) {
        const u64 b0 = *(const u64*)&sB2[n * SP + tx * 4];
        const u64 b1 = *(const u64*)&sB2[n * SP + tx * 4 + 2];
#pragma unroll
        for (int r = 0; r < 4; r++) {
            const float a = sC[(ty * 4 + r) * SP + n];
            const u64 a2 = pk2(a, a);
            gacc[r][0] = fma2(a2, b0, gacc[r][0]);
            gacc[r][1] = fma2(a2, b1, gacc[r][1]);
        }
    }
    __syncthreads();   // done reading sB2 (Bt)

    // write masked/scaled gram; load Ht[n][p] into sB2
#pragma unroll
    for (int r = 0; r < 4; r++) {
        const int i = ty * 4 + r;
        const float Si = sScan[i];
#pragma unroll
        for (int j = 0; j < 2; j++) {
            float2 v = unpk(gacc[r][j]);
            const int k0 = tx * 4 + 2 * j;
            sG[i * SP + k0]     = (i >= k0)     ? __expf(Si - sScan[k0])     * sDt[k0]     * v.x : 0.f;
            sG[i * SP + k0 + 1] = (i >= k0 + 1) ? __expf(Si - sScan[k0 + 1]) * sDt[k0 + 1] * v.y : 0.f;
        }
    }
    {
        const int n = t >> 2;
        const int p0 = (t & 3) * 16;
        const float* hsrc = g_hst + (size_t)bhc * (TC * TC) + n * TC + p0;
#pragma unroll
        for (int q = 0; q < 4; q++)
            *(float4*)&sB2[n * SP + p0 + q * 4] = *(const float4*)(hsrc + q * 4);
    }
    __syncthreads();

    // inter: aI(i,p) = sum_n C[i][n] Ht[n][p]
    u64 aI[4][2];
#pragma unroll
    for (int r = 0; r < 4; r++) { aI[r][0] = 0ull; aI[r][1] = 0ull; }
#pragma unroll
    for (int n = 0; n < TC; n++) {
        const u64 h0 = *(const u64*)&sB2[n * SP + tx * 4];
        const u64 h1 = *(const u64*)&sB2[n * SP + tx * 4 + 2];
#pragma unroll
        for (int r = 0; r < 4; r++) {
            const float a = sC[(ty * 4 + r) * SP + n];
            const u64 a2 = pk2(a, a);
            aI[r][0] = fma2(a2, h0, aI[r][0]);
            aI[r][1] = fma2(a2, h1, aI[r][1]);
        }
    }
    __syncthreads();   // done reading sB2 (Ht)

    // load X[k][p] into sB2
    {
        const int k = t >> 2;
        const int p0 = (t & 3) * 16;
        const float* xsrc = g_u + (row0 + k) * DIN_ + h * PSS + p0;
#pragma unroll
        for (int q = 0; q < 4; q++)
            *(float4*)&sB2[k * SP + p0 + q * 4] = *(const float4*)(xsrc + q * 4);
    }
    __syncthreads();

    // apply: aY(i,p) = sum_k G[i][k] X[k][p]
    u64 aY[4][2];
#pragma unroll
    for (int r = 0; r < 4; r++) { aY[r][0] = 0ull; aY[r][1] = 0ull; }
#pragma unroll
    for (int k = 0; k < TC; k++) {
        const u64 x0 = *(const u64*)&sB2[k * SP + tx * 4];
        const u64 x1 = *(const u64*)&sB2[k * SP + tx * 4 + 2];
#pragma unroll
        for (int r = 0; r < 4; r++) {
            const float g = sG[(ty * 4 + r) * SP + k];
            const u64 g2 = pk2(g, g);
            aY[r][0] = fma2(g2, x0, aY[r][0]);
            aY[r][1] = fma2(g2, x1, aY[r][1]);
        }
    }

    // epilogue
    const float Dsh = Ds[h];
#pragma unroll
    for (int r = 0; r < 4; r++) {
        const int i = ty * 4 + r;
        const float ei = sE[i];
        float* ydst = g_y + (row0 + i) * DIN_ + h * PSS;
#pragma unroll
        for (int j = 0; j < 2; j++) {
            const int p = tx * 4 + 2 * j;
            float2 y  = unpk(aY[r][j]);
            float2 yi = unpk(aI[r][j]);
            float2 xv = *(const float2*)&sB2[i * SP + p];
            float2 o;
            o.x = y.x + ei * yi.x + Dsh * xv.x;
            o.y = y.y + ei * yi.y + Dsh * xv.y;
            *(float2*)(ydst + p) = o;
        }
    }
}

#define SMEMC ((3 * TC * SP + 3 * TC) * 4)

extern "C" void kernel_launch(void* const* d_in, const int* in_sizes, int n_in,
                              void* d_out, int out_size) {
    const float* src     = (const float*)d_in[0];
    const float* ln_w    = (const float*)d_in[1];
    const float* ln_b    = (const float*)d_in[2];
    const float* W_in    = (const float*)d_in[3];
    const float* conv_w  = (const float*)d_in[4];
    const float* conv_b  = (const float*)d_in[5];
    const float* W_xproj = (const float*)d_in[6];
    const float* dt_bias = (const float*)d_in[7];
    const float* A_log   = (const float*)d_in[8];
    const float* Ds      = (const float*)d_in[9];
    const float* oln_w   = (const float*)d_in[10];
    const float* oln_b   = (const float*)d_in[11];
    const float* W_out   = (const float*)d_in[12];
    float* out = (float*)d_out;

    static bool attr_set = false;
    if (!attr_set) {
        cudaFuncSetAttribute(chunk_output_kernel,
                             cudaFuncAttributeMaxDynamicSharedMemorySize, SMEMC);
        attr_set = true;
    }

    float* xln_ptr = nullptr; float* y_ptr = nullptr; float* yln_ptr = nullptr;
    cudaGetSymbolAddress((void**)&xln_ptr, g_xln);
    cudaGetSymbolAddress((void**)&y_ptr,   g_y);
    cudaGetSymbolAddress((void**)&yln_ptr, g_yln);

    // 1) LN over D=256
    ln_kernel<D_><<<M_ / 8, 256>>>(src, ln_w, ln_b, xln_ptr);
    // 2) u0 = xln @ W_in
    gemm1_kernel<<<dim3(DIN_ / BN, M_ / BM), 256>>>(W_in);
    // 3) depthwise conv3 + bias + gelu
    conv_gelu_kernel<<<(M_ * DIN_) / 256, 256>>>(conv_w, conv_b);
    // 4) dbc = u @ W_xproj
    gemm2_kernel<<<dim3((XW_ + BN - 1) / BN, M_ / BM), 256>>>(W_xproj);
    // 5) log-decay / dt
    ddt_kernel<<<(M_ * H_) / 256, 256>>>(dt_bias, A_log);
    // 6) chunked scan
    chunk_state_kernel<<<dim3(NC_, H_, B_), 256>>>();
    state_pass_kernel<<<B_ * H_, 256>>>();
    chunk_output_kernel<<<dim3(NC_, H_, B_), 256, SMEMC>>>(Ds);
    // 7) LN over DIN=512
    ln_kernel<DIN_><<<M_ / 8, 256>>>(y_ptr, oln_w, oln_b, yln_ptr);
    // 8) out = src + yln @ W_out
    gemm3_kernel<<<dim3(D_ / BN, M_ / BM), 256>>>(W_out, src, out);
}

// round 6
// speedup vs baseline: 3.5441x; 1.2942x over previous
#include <cuda_runtime.h>
#include <math.h>

// ---------------- problem constants ----------------
#define B_   8
#define L_   2048
#define D_   256
#define DIN_ 512
#define NSS  64          // N (state dim)
#define PSS  64          // P (head dim)
#define H_   8
#define M_   (B_ * L_)   // 16384 rows
#define XW_  (H_ + 2 * NSS)  // 136
#define TC   64          // scan chunk length
#define NC_  (L_ / TC)   // 32 chunks
#define SP   68          // padded smem stride

// ---------------- scratch (device globals — no allocations allowed) ----------------
__device__ float  g_xln[M_ * D_];
__device__ float  g_u0 [M_ * DIN_];
__device__ float  g_u  [M_ * DIN_];
__device__ float  g_dbc[M_ * XW_];
__device__ float2 g_dd [M_ * H_];
__device__ float  g_y  [M_ * DIN_];
__device__ float  g_yln[M_ * DIN_];
__device__ float  g_S  [B_ * H_ * NC_ * TC * TC];
__device__ float  g_hst[B_ * H_ * NC_ * TC * TC];
__device__ float  g_alpha[B_ * H_ * NC_];

// ---------------- packed f32x2 helpers ----------------
typedef unsigned long long u64;

__device__ __forceinline__ u64 pk2(float lo, float hi) {
    u64 r;
    asm("mov.b64 %0, {%1, %2};" : "=l"(r)
        : "r"(__float_as_uint(lo)), "r"(__float_as_uint(hi)));
    return r;
}
__device__ __forceinline__ u64 fma2(u64 a, u64 b, u64 c) {
    u64 d;
    asm("fma.rn.f32x2 %0, %1, %2, %3;" : "=l"(d) : "l"(a), "l"(b), "l"(c));
    return d;
}
__device__ __forceinline__ u64 mul2(u64 a, u64 b) {
    u64 d;
    asm("mul.rn.f32x2 %0, %1, %2;" : "=l"(d) : "l"(a), "l"(b));
    return d;
}
__device__ __forceinline__ float2 unpk(u64 v) {
    unsigned lo, hi;
    asm("mov.b64 {%0, %1}, %2;" : "=r"(lo), "=r"(hi) : "l"(v));
    return make_float2(__uint_as_float(lo), __uint_as_float(hi));
}

// ---------------- LayerNorm: one warp per row ----------------
template <int W>
__global__ void ln_kernel(const float* __restrict__ in,
                          const float* __restrict__ gw,
                          const float* __restrict__ gb,
                          float* __restrict__ out) {
    const int warp = threadIdx.x >> 5, lane = threadIdx.x & 31;
    const int row = blockIdx.x * (blockDim.x >> 5) + warp;
    const float* p = in + (size_t)row * W;
    constexpr int C = W / 128;
    float4 v[C];
    float s = 0.f, s2 = 0.f;
#pragma unroll
    for (int c = 0; c < C; c++) {
        v[c] = *(const float4*)(p + c * 128 + lane * 4);
        s  += v[c].x + v[c].y + v[c].z + v[c].w;
        s2 += v[c].x * v[c].x + v[c].y * v[c].y + v[c].z * v[c].z + v[c].w * v[c].w;
    }
#pragma unroll
    for (int o = 16; o > 0; o >>= 1) {
        s  += __shfl_xor_sync(0xffffffffu, s, o);
        s2 += __shfl_xor_sync(0xffffffffu, s2, o);
    }
    const float mean = s * (1.f / W);
    const float var  = s2 * (1.f / W) - mean * mean;
    const float inv  = rsqrtf(var + 1e-5f);
    float* q = out + (size_t)row * W;
#pragma unroll
    for (int c = 0; c < C; c++) {
        const int i = c * 128 + lane * 4;
        float4 w4 = *(const float4*)(gw + i);
        float4 b4 = *(const float4*)(gb + i);
        float4 r;
        r.x = (v[c].x - mean) * inv * w4.x + b4.x;
        r.y = (v[c].y - mean) * inv * w4.y + b4.y;
        r.z = (v[c].z - mean) * inv * w4.z + b4.z;
        r.w = (v[c].w - mean) * inv * w4.w + b4.w;
        *(float4*)(q + i) = r;
    }
}

// ================= TF32 tensor-core GEMM =================
// C[M,N] = A[M,K] @ B[K,N] (+ addend). 128x64x32 tiles, 256 thr (8 warps),
// warp tile 32x32 via mma.sync.m16n8k8.tf32.
#define TBM 128
#define TBN 64
#define TBK 32
#define ASTR 36   // As[m][k] stride: fragment bank = g*4+km -> conflict-free
#define BSTR 72   // Bs[k][n] stride: fragment bank = km*8+g -> conflict-free

__device__ __forceinline__ unsigned f2tf(float f) {
    unsigned r;
    asm("cvt.rna.tf32.f32 %0, %1;" : "=r"(r) : "f"(f));
    return r;
}

template <bool NGUARD, bool ADD>
__device__ __forceinline__ void tgemm_dev(int M, int N, int K,
                                          const float* __restrict__ A,
                                          const float* __restrict__ Bm,
                                          float* __restrict__ C,
                                          const float* __restrict__ addend) {
    __shared__ __align__(16) unsigned As[TBM][ASTR];
    __shared__ __align__(16) unsigned Bs[TBK][BSTR];

    const int tid = threadIdx.x;
    const int bm = blockIdx.y * TBM;
    const int bn = blockIdx.x * TBN;
    const int am = tid >> 1, ak = (tid & 1) * 16;     // A staging: row am, 16 cols
    const int bk = tid >> 3, bn0 = (tid & 7) * 8;     // B staging: row bk, 8 cols
    const int wid = tid >> 5, lane = tid & 31;
    const int g = lane >> 2, km = lane & 3;
    const int wm = (wid & 3) * 32, wn = (wid >> 2) * 32;

    float acc[2][4][4];
#pragma unroll
    for (int mi = 0; mi < 2; mi++)
#pragma unroll
        for (int nj = 0; nj < 4; nj++)
#pragma unroll
            for (int q = 0; q < 4; q++) acc[mi][nj][q] = 0.f;

    const float* Aptr = A + (size_t)(bm + am) * K + ak;
    const float* Bptr = Bm + (size_t)bk * N + bn + bn0;

    const int nk = K / TBK;
    for (int kt = 0; kt < nk; kt++) {
        float4 ra[4];
#pragma unroll
        for (int q = 0; q < 4; q++)
            ra[q] = *(const float4*)(Aptr + kt * TBK + q * 4);
        float4 rb[2];
#pragma unroll
        for (int q = 0; q < 2; q++) {
            if (!NGUARD || (bn + bn0 + q * 4) < N)
                rb[q] = *(const float4*)(Bptr + (size_t)kt * TBK * N + q * 4);
            else
                rb[q] = make_float4(0.f, 0.f, 0.f, 0.f);
        }
        __syncthreads();
#pragma unroll
        for (int q = 0; q < 4; q++) {
            As[am][ak + q * 4 + 0] = f2tf(ra[q].x);
            As[am][ak + q * 4 + 1] = f2tf(ra[q].y);
            As[am][ak + q * 4 + 2] = f2tf(ra[q].z);
            As[am][ak + q * 4 + 3] = f2tf(ra[q].w);
        }
#pragma unroll
        for (int q = 0; q < 2; q++) {
            Bs[bk][bn0 + q * 4 + 0] = f2tf(rb[q].x);
            Bs[bk][bn0 + q * 4 + 1] = f2tf(rb[q].y);
            Bs[bk][bn0 + q * 4 + 2] = f2tf(rb[q].z);
            Bs[bk][bn0 + q * 4 + 3] = f2tf(rb[q].w);
        }
        __syncthreads();

#pragma unroll
        for (int ks = 0; ks < 4; ks++) {
            const int k0 = ks * 8;
            unsigned af[2][4], bf[4][2];
#pragma unroll
            for (int mi = 0; mi < 2; mi++) {
                const int mr = wm + mi * 16 + g;
                af[mi][0] = As[mr][k0 + km];
                af[mi][1] = As[mr + 8][k0 + km];
                af[mi][2] = As[mr][k0 + km + 4];
                af[mi][3] = As[mr + 8][k0 + km + 4];
            }
#pragma unroll
            for (int nj = 0; nj < 4; nj++) {
                const int nc = wn + nj * 8 + g;
                bf[nj][0] = Bs[k0 + km][nc];
                bf[nj][1] = Bs[k0 + km + 4][nc];
            }
#pragma unroll
            for (int mi = 0; mi < 2; mi++)
#pragma unroll
                for (int nj = 0; nj < 4; nj++)
                    asm volatile(
                        "mma.sync.aligned.m16n8k8.row.col.f32.tf32.tf32.f32 "
                        "{%0,%1,%2,%3}, {%4,%5,%6,%7}, {%8,%9}, {%0,%1,%2,%3};"
                        : "+f"(acc[mi][nj][0]), "+f"(acc[mi][nj][1]),
                          "+f"(acc[mi][nj][2]), "+f"(acc[mi][nj][3])
                        : "r"(af[mi][0]), "r"(af[mi][1]),
                          "r"(af[mi][2]), "r"(af[mi][3]),
                          "r"(bf[nj][0]), "r"(bf[nj][1]));
        }
    }

    // epilogue: c0,c1 at (row, col km*2, +1), c2,c3 at row+8
#pragma unroll
    for (int mi = 0; mi < 2; mi++) {
        const int r0 = bm + wm + mi * 16 + g;
#pragma unroll
        for (int nj = 0; nj < 4; nj++) {
            const int col = bn + wn + nj * 8 + km * 2;
            if (NGUARD && col >= N) continue;
            const size_t o0 = (size_t)r0 * N + col;
            const size_t o1 = (size_t)(r0 + 8) * N + col;
            float2 v0 = make_float2(acc[mi][nj][0], acc[mi][nj][1]);
            float2 v1 = make_float2(acc[mi][nj][2], acc[mi][nj][3]);
            if (ADD) {
                float2 s0 = *(const float2*)(addend + o0);
                float2 s1 = *(const float2*)(addend + o1);
                v0.x += s0.x; v0.y += s0.y;
                v1.x += s1.x; v1.y += s1.y;
            }
            *(float2*)(C + o0) = v0;
            *(float2*)(C + o1) = v1;
        }
    }
}

__global__ void __launch_bounds__(256) gemm1_kernel(const float* __restrict__ W_in) {
    tgemm_dev<false, false>(M_, DIN_, D_, g_xln, W_in, g_u0, nullptr);
}
__global__ void __launch_bounds__(256) gemm2_kernel(const float* __restrict__ W_xproj) {
    tgemm_dev<true, false>(M_, XW_, DIN_, g_u, W_xproj, g_dbc, nullptr);
}
__global__ void __launch_bounds__(256) gemm3_kernel(const float* __restrict__ W_out,
                                                    const float* __restrict__ src,
                                                    float* __restrict__ out) {
    tgemm_dev<false, true>(M_, D_, DIN_, g_yln, W_out, out, src);
}

// ---------------- depthwise conv3 + bias + exact GELU ----------------
__global__ void conv_gelu_kernel(const float* __restrict__ cw,
                                 const float* __restrict__ cb) {
    const int idx = blockIdx.x * blockDim.x + threadIdx.x;
    if (idx >= M_ * DIN_) return;
    const int c = idx & (DIN_ - 1);
    const int m = idx >> 9;
    const int l = m & (L_ - 1);
    const float w0 = cw[c * 3 + 0], w1 = cw[c * 3 + 1], w2 = cw[c * 3 + 2];
    const float xm = (l > 0)      ? g_u0[idx - DIN_] : 0.f;
    const float x0 = g_u0[idx];
    const float xp = (l < L_ - 1) ? g_u0[idx + DIN_] : 0.f;
    const float v = w0 * xm + w1 * x0 + w2 * xp + cb[c];
    g_u[idx] = 0.5f * v * (1.f + erff(v * 0.7071067811865476f));
}

// ---------------- (la = -dt*exp(A_log), dt = softplus) ----------------
__global__ void ddt_kernel(const float* __restrict__ dt_bias,
                           const float* __restrict__ A_log) {
    const int idx = blockIdx.x * blockDim.x + threadIdx.x;
    if (idx >= M_ * H_) return;
    const int h = idx & 7;
    const int m = idx >> 3;
    const float x = g_dbc[(size_t)m * XW_ + h] + dt_bias[h];
    const float dt = (x > 0.f) ? x + log1pf(expf(-x)) : log1pf(expf(x));
    const float la = -dt * expf(A_log[h]);
    g_dd[idx] = make_float2(la, dt);
}

// ================= chunked selective scan =================
__global__ void __launch_bounds__(256) chunk_state_kernel() {
    __shared__ __align__(16) float sBt[TC][SP];
    __shared__ __align__(16) float sXc[TC][SP];
    __shared__ float sScan[TC], sDt[TC];

    const int c = blockIdx.x, h = blockIdx.y, b = blockIdx.z;
    const int t = threadIdx.x;
    const size_t row0 = (size_t)b * L_ + (size_t)c * TC;
    const int bhc = (b * H_ + h) * NC_ + c;

    if (t < TC) {
        float2 dd = g_dd[(row0 + t) * H_ + h];
        sScan[t] = dd.x; sDt[t] = dd.y;
    }
    __syncthreads();
    if (t == 0) {
        float s = 0.f;
#pragma unroll 1
        for (int i = 0; i < TC; i++) { s += sScan[i]; sScan[i] = s; }
    }
    __syncthreads();

    {
        const int k = t >> 2;
        const int n0 = (t & 3) * 16;
        const float* bsrc = g_dbc + (row0 + k) * XW_ + H_ + n0;
        const float Send = sScan[TC - 1];
        const float coef = __expf(Send - sScan[k]) * sDt[k];
        const float* xsrc = g_u + (row0 + k) * DIN_ + h * PSS + n0;
#pragma unroll
        for (int q = 0; q < 4; q++) {
            float4 v = *(const float4*)(bsrc + q * 4);
            const int n = n0 + q * 4;
            sBt[n + 0][k] = v.x; sBt[n + 1][k] = v.y;
            sBt[n + 2][k] = v.z; sBt[n + 3][k] = v.w;
            float4 x = *(const float4*)(xsrc + q * 4);
            x.x *= coef; x.y *= coef; x.z *= coef; x.w *= coef;
            *(float4*)&sXc[k][n0 + q * 4] = x;
        }
    }
    if (t == 0) g_alpha[bhc] = __expf(sScan[TC - 1]);
    __syncthreads();

    const int ty = t >> 4, tx = t & 15;
    u64 acc[4][2];
#pragma unroll
    for (int r = 0; r < 4; r++) { acc[r][0] = 0ull; acc[r][1] = 0ull; }
#pragma unroll
    for (int k = 0; k < TC; k++) {
        const u64 x0 = *(const u64*)&sXc[k][tx * 4];
        const u64 x1 = *(const u64*)&sXc[k][tx * 4 + 2];
#pragma unroll
        for (int r = 0; r < 4; r++) {
            const float bv = sBt[ty * 4 + r][k];
            const u64 b2 = pk2(bv, bv);
            acc[r][0] = fma2(b2, x0, acc[r][0]);
            acc[r][1] = fma2(b2, x1, acc[r][1]);
        }
    }
    float* dst = g_S + (size_t)bhc * (TC * TC);
#pragma unroll
    for (int r = 0; r < 4; r++) {
        const int n = ty * 4 + r;
        float2 f0 = unpk(acc[r][0]), f1 = unpk(acc[r][1]);
        *(float4*)(dst + n * TC + tx * 4) = make_float4(f0.x, f0.y, f1.x, f1.y);
    }
}

__global__ void __launch_bounds__(256) state_pass_kernel() {
    const int bh = blockIdx.x;
    const int t = threadIdx.x;
    float4 hv[4];
#pragma unroll
    for (int q = 0; q < 4; q++) hv[q] = make_float4(0.f, 0.f, 0.f, 0.f);
    const size_t base = (size_t)bh * NC_ * (TC * TC);
#pragma unroll 1
    for (int c = 0; c < NC_; c++) {
        const float alpha = g_alpha[bh * NC_ + c];
        float* hst = g_hst + base + (size_t)c * (TC * TC);
        const float* S = g_S + base + (size_t)c * (TC * TC);
#pragma unroll
        for (int q = 0; q < 4; q++) {
            const int off = (q * 256 + t) * 4;
            *(float4*)(hst + off) = hv[q];
            float4 s = *(const float4*)(S + off);
            hv[q].x = alpha * hv[q].x + s.x;
            hv[q].y = alpha * hv[q].y + s.y;
            hv[q].z = alpha * hv[q].z + s.z;
            hv[q].w = alpha * hv[q].w + s.w;
        }
    }
}

__global__ void __launch_bounds__(256) chunk_output_kernel(const float* __restrict__ Ds) {
    extern __shared__ __align__(16) float dynsmem[];
    float* sC  = dynsmem;
    float* sB2 = sC + TC * SP;
    float* sG  = sB2 + TC * SP;
    float* sScan = sG + TC * SP;
    float* sDt   = sScan + TC;
    float* sE    = sDt + TC;

    const int c = blockIdx.x, h = blockIdx.y, b = blockIdx.z;
    const int t = threadIdx.x;
    const size_t row0 = (size_t)b * L_ + (size_t)c * TC;
    const int bhc = (b * H_ + h) * NC_ + c;

    if (t < TC) {
        float2 dd = g_dd[(row0 + t) * H_ + h];
        sScan[t] = dd.x; sDt[t] = dd.y;
    }
    __syncthreads();
    if (t == 0) {
        float s = 0.f;
#pragma unroll 1
        for (int i = 0; i < TC; i++) { s += sScan[i]; sScan[i] = s; }
    }
    __syncthreads();
    if (t < TC) sE[t] = __expf(sScan[t]);

    {
        const int k = t >> 2;
        const int n0 = (t & 3) * 16;
        const float* csrc = g_dbc + (row0 + k) * XW_ + H_ + NSS + n0;
        const float* bsrc = g_dbc + (row0 + k) * XW_ + H_ + n0;
#pragma unroll
        for (int q = 0; q < 4; q++) {
            *(float4*)&sC[k * SP + n0 + q * 4] = *(const float4*)(csrc + q * 4);
            float4 v = *(const float4*)(bsrc + q * 4);
            const int n = n0 + q * 4;
            sB2[(n + 0) * SP + k] = v.x; sB2[(n + 1) * SP + k] = v.y;
            sB2[(n + 2) * SP + k] = v.z; sB2[(n + 3) * SP + k] = v.w;
        }
    }
    __syncthreads();

    const int ty = t >> 4, tx = t & 15;

    u64 gacc[4][2];
#pragma unroll
    for (int r = 0; r < 4; r++) { gacc[r][0] = 0ull; gacc[r][1] = 0ull; }
#pragma unroll
    for (int n = 0; n < TC; n++) {
        const u64 b0 = *(const u64*)&sB2[n * SP + tx * 4];
        const u64 b1 = *(const u64*)&sB2[n * SP + tx * 4 + 2];
#pragma unroll
        for (int r = 0; r < 4; r++) {
            const float a = sC[(ty * 4 + r) * SP + n];
            const u64 a2 = pk2(a, a);
            gacc[r][0] = fma2(a2, b0, gacc[r][0]);
            gacc[r][1] = fma2(a2, b1, gacc[r][1]);
        }
    }
    __syncthreads();

#pragma unroll
    for (int r = 0; r < 4; r++) {
        const int i = ty * 4 + r;
        const float Si = sScan[i];
#pragma unroll
        for (int j = 0; j < 2; j++) {
            float2 v = unpk(gacc[r][j]);
            const int k0 = tx * 4 + 2 * j;
            sG[i * SP + k0]     = (i >= k0)     ? __expf(Si - sScan[k0])     * sDt[k0]     * v.x : 0.f;
            sG[i * SP + k0 + 1] = (i >= k0 + 1) ? __expf(Si - sScan[k0 + 1]) * sDt[k0 + 1] * v.y : 0.f;
        }
    }
    {
        const int n = t >> 2;
        const int p0 = (t & 3) * 16;
        const float* hsrc = g_hst + (size_t)bhc * (TC * TC) + n * TC + p0;
#pragma unroll
        for (int q = 0; q < 4; q++)
            *(float4*)&sB2[n * SP + p0 + q * 4] = *(const float4*)(hsrc + q * 4);
    }
    __syncthreads();

    u64 aI[4][2];
#pragma unroll
    for (int r = 0; r < 4; r++) { aI[r][0] = 0ull; aI[r][1] = 0ull; }
#pragma unroll
    for (int n = 0; n < TC; n++) {
        const u64 h0 = *(const u64*)&sB2[n * SP + tx * 4];
        const u64 h1 = *(const u64*)&sB2[n * SP + tx * 4 + 2];
#pragma unroll
        for (int r = 0; r < 4; r++) {
            const float a = sC[(ty * 4 + r) * SP + n];
            const u64 a2 = pk2(a, a);
            aI[r][0] = fma2(a2, h0, aI[r][0]);
            aI[r][1] = fma2(a2, h1, aI[r][1]);
        }
    }
    __syncthreads();

    {
        const int k = t >> 2;
        const int p0 = (t & 3) * 16;
        const float* xsrc = g_u + (row0 + k) * DIN_ + h * PSS + p0;
#pragma unroll
        for (int q = 0; q < 4; q++)
            *(float4*)&sB2[k * SP + p0 + q * 4] = *(const float4*)(xsrc + q * 4);
    }
    __syncthreads();

    u64 aY[4][2];
#pragma unroll
    for (int r = 0; r < 4; r++) { aY[r][0] = 0ull; aY[r][1] = 0ull; }
#pragma unroll
    for (int k = 0; k < TC; k++) {
        const u64 x0 = *(const u64*)&sB2[k * SP + tx * 4];
        const u64 x1 = *(const u64*)&sB2[k * SP + tx * 4 + 2];
#pragma unroll
        for (int r = 0; r < 4; r++) {
            const float g = sG[(ty * 4 + r) * SP + k];
            const u64 g2 = pk2(g, g);
            aY[r][0] = fma2(g2, x0, aY[r][0]);
            aY[r][1] = fma2(g2, x1, aY[r][1]);
        }
    }

    const float Dsh = Ds[h];
#pragma unroll
    for (int r = 0; r < 4; r++) {
        const int i = ty * 4 + r;
        const float ei = sE[i];
        float* ydst = g_y + (row0 + i) * DIN_ + h * PSS;
#pragma unroll
        for (int j = 0; j < 2; j++) {
            const int p = tx * 4 + 2 * j;
            float2 y  = unpk(aY[r][j]);
            float2 yi = unpk(aI[r][j]);
            float2 xv = *(const float2*)&sB2[i * SP + p];
            float2 o;
            o.x = y.x + ei * yi.x + Dsh * xv.x;
            o.y = y.y + ei * yi.y + Dsh * xv.y;
            *(float2*)(ydst + p) = o;
        }
    }
}

#define SMEMC ((3 * TC * SP + 3 * TC) * 4)

extern "C" void kernel_launch(void* const* d_in, const int* in_sizes, int n_in,
                              void* d_out, int out_size) {
    const float* src     = (const float*)d_in[0];
    const float* ln_w    = (const float*)d_in[1];
    const float* ln_b    = (const float*)d_in[2];
    const float* W_in    = (const float*)d_in[3];
    const float* conv_w  = (const float*)d_in[4];
    const float* conv_b  = (const float*)d_in[5];
    const float* W_xproj = (const float*)d_in[6];
    const float* dt_bias = (const float*)d_in[7];
    const float* A_log   = (const float*)d_in[8];
    const float* Ds      = (const float*)d_in[9];
    const float* oln_w   = (const float*)d_in[10];
    const float* oln_b   = (const float*)d_in[11];
    const float* W_out   = (const float*)d_in[12];
    float* out = (float*)d_out;

    static bool attr_set = false;
    if (!attr_set) {
        cudaFuncSetAttribute(chunk_output_kernel,
                             cudaFuncAttributeMaxDynamicSharedMemorySize, SMEMC);
        attr_set = true;
    }

    float* xln_ptr = nullptr; float* y_ptr = nullptr; float* yln_ptr = nullptr;
    cudaGetSymbolAddress((void**)&xln_ptr, g_xln);
    cudaGetSymbolAddress((void**)&y_ptr,   g_y);
    cudaGetSymbolAddress((void**)&yln_ptr, g_yln);

    // 1) LN over D=256
    ln_kernel<D_><<<M_ / 8, 256>>>(src, ln_w, ln_b, xln_ptr);
    // 2) u0 = xln @ W_in  (tf32 tensor)
    gemm1_kernel<<<dim3(DIN_ / TBN, M_ / TBM), 256>>>(W_in);
    // 3) depthwise conv3 + bias + gelu
    conv_gelu_kernel<<<(M_ * DIN_) / 256, 256>>>(conv_w, conv_b);
    // 4) dbc = u @ W_xproj (tf32 tensor, N guarded)
    gemm2_kernel<<<dim3((XW_ + TBN - 1) / TBN, M_ / TBM), 256>>>(W_xproj);
    // 5) log-decay / dt
    ddt_kernel<<<(M_ * H_) / 256, 256>>>(dt_bias, A_log);
    // 6) chunked scan
    chunk_state_kernel<<<dim3(NC_, H_, B_), 256>>>();
    state_pass_kernel<<<B_ * H_, 256>>>();
    chunk_output_kernel<<<dim3(NC_, H_, B_), 256, SMEMC>>>(Ds);
    // 7) LN over DIN=512
    ln_kernel<DIN_><<<M_ / 8, 256>>>(y_ptr, oln_w, oln_b, yln_ptr);
    // 8) out = src + yln @ W_out (tf32 tensor, fused residual)
    gemm3_kernel<<<dim3(D_ / TBN, M_ / TBM), 256>>>(W_out, src, out);
}